// round 16
// baseline (speedup 1.0000x reference)
#include <cuda_runtime.h>
#include <cuda_fp16.h>
#include <math.h>
#include <stdint.h>

#define BC        1024       // 8 * 128 merged batch*channel
#define LIN       65536
#define LOUT      16384
#define KNB       9
#define CHUNK_BC  256        // bc per pipeline chunk
#define NCHUNK    (BC / CHUNK_BC)          // 4
#define CHUNK_EL  ((size_t)LIN * CHUNK_BC) // halves per chunk buffer (32 MB)

#define GRID      4096       // transpose tiles per chunk == gather sub-tasks per chunk

// smem sub-tile bases: blk(rblk, cblk) = cblk*2120 + rblk*1057 floats.
// 1057 = 32*33 + 1: shifts row-block 1 by +1 bank so the store-phase LDS
// pattern (even rows lanes 0-15, base+1 rows lanes 16-31) covers 32 banks.
#define CBSTRIDE  2120
#define RBSTRIDE  1057
#define SMEM_WORDS (CBSTRIDE + RBSTRIDE + 31*33 + 31 + 1)   // 4232 floats, 16.9 KB

// 64 MB ping-pong scratch, mostly L2-resident: buf[p][i][bcp], bcp < 256
__device__ __half g_buf[2 * CHUNK_EL];

// ---------------------------------------------------------------------------
// Transpose one 64bc x 64i tile of chunk tc into buf[tc&1] (R15 scheme:
// fully conflict-free STS + dual-LDS via the +1-bank row-block offset).
// ---------------------------------------------------------------------------
__device__ __forceinline__ void do_transpose(const float* __restrict__ x,
                                             float* sm_raw, int tc, int tidx,
                                             int w, int lane) {
    const int iBase  = (tidx >> 2) * 64;
    const int bcT    = tidx & 3;
    const int bcBase = tc * CHUNK_BC + bcT * 64;

    // load: warp w owns bc rows w*8..w*8+7; per row 2 x LDG.32 (128B coalesced)
    #pragma unroll
    for (int u = 0; u < 8; u++) {
        int r    = w * 8 + u;
        int rblk = r >> 5, rr = r & 31;
        const float* xrow = x + (size_t)(bcBase + r) * LIN + iBase;
        #pragma unroll
        for (int cb = 0; cb < 2; cb++) {
            float v = __ldcs(xrow + cb * 32 + lane);
            sm_raw[cb * CBSTRIDE + rblk * RBSTRIDE + rr * 33 + lane] = v;
        }
    }
    __syncthreads();

    // store: warp w owns i = w*8..w*8+7; lane = bc-pair; STG 128B contiguous/i
    const int rblk = lane >> 4;
    const int rr_e = (2 * lane) & 31;
    const int rr_o = (2 * lane + 1) & 31;
    __half2* dst = (__half2*)(g_buf + (size_t)(tc & 1) * CHUNK_EL)
                   + bcT * 32 + lane;
    #pragma unroll
    for (int s = 0; s < 8; s++) {
        int i  = w * 8 + s;
        int cb = i >> 5, ii = i & 31;
        const float* base = sm_raw + cb * CBSTRIDE + rblk * RBSTRIDE;
        float ve = base[rr_e * 33 + ii];
        float vo = base[rr_o * 33 + ii];
        dst[(size_t)(iBase + i) * 128] = __floats2half2_rn(ve, vo);
    }
}

// ---------------------------------------------------------------------------
// Gather sub-task: 16 l x 64 bc of chunk gc from buf[gc&1]. Warp = 2 l's;
// 18 independent 128B gathers batched per warp iteration.
// ---------------------------------------------------------------------------
__device__ __forceinline__ void do_gather(const int* __restrict__ nb,
                                          float* __restrict__ out,
                                          float* sm_raw, int gc, int gidx,
                                          int t, int w, int lane) {
    __half* s_g = (__half*)sm_raw;        // [16][66] halves = 2.1 KB overlay

    const int lTile = gidx >> 2;
    const int sub   = gidx & 3;
    const int lBase = lTile * 16;

    // lanes 0-17 hold idx(l = lBase + w*2 + (lane&1), k = lane>>1)
    int myIdx = 0;
    if (lane < 2 * KNB)
        myIdx = __ldg(nb + (size_t)(lane >> 1) * LOUT + lBase + w * 2 + (lane & 1));

    const __half2* xb = (const __half2*)(g_buf + (size_t)(gc & 1) * CHUNK_EL)
                        + sub * 32 + lane;

    __half2 acc[2];
    #pragma unroll
    for (int m = 0; m < 2; m++) {
        __half2 v[KNB];
        #pragma unroll
        for (int k = 0; k < KNB; k++) {
            int i = __shfl_sync(0xffffffffu, myIdx, 2 * k + m);
            v[k] = __ldg(xb + (size_t)i * 128);   // 128B coalesced per warp
        }
        __half2 m01 = __hmax2(v[0], v[1]);
        __half2 m23 = __hmax2(v[2], v[3]);
        __half2 m45 = __hmax2(v[4], v[5]);
        __half2 m67 = __hmax2(v[6], v[7]);
        m01 = __hmax2(m01, m23);
        m45 = __hmax2(m45, m67);
        acc[m] = __hmax2(__hmax2(m01, m45), v[8]);
    }
    __half2* so = (__half2*)s_g;
    so[(w * 2 + 0) * 33 + lane] = acc[0];   // bank (2w+lane)%32: conflict-free
    so[(w * 2 + 1) * 33 + lane] = acc[1];
    __syncthreads();

    // writeback: t -> l = t&15, bc group (t>>4)*4; 64B coalesced segments
    const int l = t & 15;
    const int g = t >> 4;
    float* ob = out + (size_t)(gc * CHUNK_BC + sub * 64 + g * 4) * LOUT + lBase + l;
    #pragma unroll
    for (int b = 0; b < 4; b++)
        __stcs(ob + (size_t)b * LOUT, __half2float(s_g[l * 66 + g * 4 + b]));
}

// ---------------------------------------------------------------------------
// Combined kernel. Mixed launches: EVERY CTA does one transpose tile (chunk
// tc) and one gather sub-task (chunk gc, other ping-pong buffer). Phase order
// alternates by CTA parity so each SM carries both DRAM-streaming and
// L2-gather warps from the start.
// ---------------------------------------------------------------------------
__global__ __launch_bounds__(256) void pool_kernel(const float* __restrict__ x,
                                                   const int*   __restrict__ nb,
                                                   float*       __restrict__ out,
                                                   int gc, int tc) {
    __shared__ __align__(16) float sm_raw[SMEM_WORDS];

    const int t    = threadIdx.x;
    const int w    = t >> 5;
    const int lane = t & 31;
    const int bid  = blockIdx.x;

    if (gc >= 0 && tc >= 0) {
        if (bid & 1) {
            do_gather(nb, out, sm_raw, gc, bid, t, w, lane);
            __syncthreads();
            do_transpose(x, sm_raw, tc, bid, w, lane);
        } else {
            do_transpose(x, sm_raw, tc, bid, w, lane);
            __syncthreads();
            do_gather(nb, out, sm_raw, gc, bid, t, w, lane);
        }
    } else if (tc >= 0) {
        do_transpose(x, sm_raw, tc, bid, w, lane);
    } else {
        do_gather(nb, out, sm_raw, gc, bid, t, w, lane);
    }
}

// ---------------------------------------------------------------------------
extern "C" void kernel_launch(void* const* d_in, const int* in_sizes, int n_in,
                              void* d_out, int out_size) {
    const float* x   = (const float*)d_in[0];
    const int*   nb  = (const int*)d_in[1];
    float*       out = (float*)d_out;

    (void)in_sizes; (void)n_in; (void)out_size;

    pool_kernel<<<GRID, 256>>>(x, nb, out, -1, 0);               // T0
    for (int c = 0; c < NCHUNK - 1; c++)
        pool_kernel<<<GRID, 256>>>(x, nb, out, c, c + 1);        // fused Gc+Tc+1
    pool_kernel<<<GRID, 256>>>(x, nb, out, NCHUNK - 1, -1);      // G_last
}

// round 17
// speedup vs baseline: 1.0216x; 1.0216x over previous
#include <cuda_runtime.h>
#include <cuda_fp16.h>
#include <math.h>
#include <stdint.h>

#define BC        1024       // 8 * 128 merged batch*channel
#define LIN       65536
#define LOUT      16384
#define KNB       9
#define CHUNK_BC  256        // bc per pipeline chunk
#define NCHUNK    (BC / CHUNK_BC)          // 4
#define CHUNK_EL  ((size_t)LIN * CHUNK_BC) // halves per chunk buffer (32 MB)

#define GRID      4096       // transpose tiles per chunk == gather sub-tasks per chunk

// smem sub-tile bases: blk(rblk, cblk) = cblk*2120 + rblk*1057 floats.
// 1057 = 32*33 + 1: shifts row-block 1 by +1 bank so the store-phase LDS
// pattern (even rows lanes 0-15, base+1 rows lanes 16-31) covers 32 banks.
#define CBSTRIDE  2120
#define RBSTRIDE  1057
#define SMEM_WORDS (CBSTRIDE + RBSTRIDE + 31*33 + 31 + 1)   // 4232 floats, 16.9 KB

// 64 MB ping-pong scratch, mostly L2-resident: buf[p][i][bcp], bcp < 256
__device__ __half g_buf[2 * CHUNK_EL];

// ---------------------------------------------------------------------------
// Transpose one 64bc x 64i tile of chunk tc into buf[tc&1] (fully
// conflict-free STS + dual-LDS via the +1-bank row-block offset).
// ---------------------------------------------------------------------------
__device__ __forceinline__ void do_transpose(const float* __restrict__ x,
                                             float* sm_raw, int tc, int tidx,
                                             int w, int lane) {
    const int iBase  = (tidx >> 2) * 64;
    const int bcT    = tidx & 3;
    const int bcBase = tc * CHUNK_BC + bcT * 64;

    // load: warp w owns bc rows w*8..w*8+7; per row 2 x LDG.32 (128B coalesced)
    #pragma unroll
    for (int u = 0; u < 8; u++) {
        int r    = w * 8 + u;
        int rblk = r >> 5, rr = r & 31;
        const float* xrow = x + (size_t)(bcBase + r) * LIN + iBase;
        #pragma unroll
        for (int cb = 0; cb < 2; cb++) {
            float v = __ldcs(xrow + cb * 32 + lane);
            sm_raw[cb * CBSTRIDE + rblk * RBSTRIDE + rr * 33 + lane] = v;
        }
    }
    __syncthreads();

    // store: warp w owns i = w*8..w*8+7; lane = bc-pair; STG 128B contiguous/i
    const int rblk = lane >> 4;
    const int rr_e = (2 * lane) & 31;
    const int rr_o = (2 * lane + 1) & 31;
    __half2* dst = (__half2*)(g_buf + (size_t)(tc & 1) * CHUNK_EL)
                   + bcT * 32 + lane;
    #pragma unroll
    for (int s = 0; s < 8; s++) {
        int i  = w * 8 + s;
        int cb = i >> 5, ii = i & 31;
        const float* base = sm_raw + cb * CBSTRIDE + rblk * RBSTRIDE;
        float ve = base[rr_e * 33 + ii];
        float vo = base[rr_o * 33 + ii];
        dst[(size_t)(iBase + i) * 128] = __floats2half2_rn(ve, vo);
    }
}

// ---------------------------------------------------------------------------
// Gather sub-task: 16 l x 64 bc of chunk gc from buf[gc&1]. Warp = 2 l's;
// 18 independent 128B gathers batched per warp iteration.
// ---------------------------------------------------------------------------
__device__ __forceinline__ void do_gather(const int* __restrict__ nb,
                                          float* __restrict__ out,
                                          float* sm_raw, int gc, int gidx,
                                          int t, int w, int lane) {
    __half* s_g = (__half*)sm_raw;        // [16][66] halves overlay

    const int lTile = gidx >> 2;
    const int sub   = gidx & 3;
    const int lBase = lTile * 16;

    // lanes 0-17 hold idx(l = lBase + w*2 + (lane&1), k = lane>>1)
    int myIdx = 0;
    if (lane < 2 * KNB)
        myIdx = __ldg(nb + (size_t)(lane >> 1) * LOUT + lBase + w * 2 + (lane & 1));

    const __half2* xb = (const __half2*)(g_buf + (size_t)(gc & 1) * CHUNK_EL)
                        + sub * 32 + lane;

    __half2 acc[2];
    #pragma unroll
    for (int m = 0; m < 2; m++) {
        __half2 v[KNB];
        #pragma unroll
        for (int k = 0; k < KNB; k++) {
            int i = __shfl_sync(0xffffffffu, myIdx, 2 * k + m);
            v[k] = __ldg(xb + (size_t)i * 128);   // 128B coalesced per warp
        }
        __half2 m01 = __hmax2(v[0], v[1]);
        __half2 m23 = __hmax2(v[2], v[3]);
        __half2 m45 = __hmax2(v[4], v[5]);
        __half2 m67 = __hmax2(v[6], v[7]);
        m01 = __hmax2(m01, m23);
        m45 = __hmax2(m45, m67);
        acc[m] = __hmax2(__hmax2(m01, m45), v[8]);
    }
    __half2* so = (__half2*)s_g;
    so[(w * 2 + 0) * 33 + lane] = acc[0];   // bank (2w+lane)%32: conflict-free
    so[(w * 2 + 1) * 33 + lane] = acc[1];
    __syncthreads();

    // writeback: t -> l = t&15, bc group (t>>4)*4; 64B coalesced segments
    const int l = t & 15;
    const int g = t >> 4;
    float* ob = out + (size_t)(gc * CHUNK_BC + sub * 64 + g * 4) * LOUT + lBase + l;
    #pragma unroll
    for (int b = 0; b < 4; b++)
        __stcs(ob + (size_t)b * LOUT, __half2float(s_g[l * 66 + g * 4 + b]));
}

// ---------------------------------------------------------------------------
// Combined kernel. Mixed launches: EVERY CTA does one transpose tile (chunk
// tc) and one gather sub-task (chunk gc, other ping-pong buffer). Phase order
// alternates by CTA parity so each SM carries both DRAM-streaming and
// L2-gather warps from the start. minBlocksPerMP=8 pins regs to 32 so
// occupancy stays at 8 CTAs/SM (the R16 fusion drifted to 40 regs -> 6).
// ---------------------------------------------------------------------------
__global__ __launch_bounds__(256, 8) void pool_kernel(const float* __restrict__ x,
                                                      const int*   __restrict__ nb,
                                                      float*       __restrict__ out,
                                                      int gc, int tc) {
    __shared__ __align__(16) float sm_raw[SMEM_WORDS];

    const int t    = threadIdx.x;
    const int w    = t >> 5;
    const int lane = t & 31;
    const int bid  = blockIdx.x;

    if (gc >= 0 && tc >= 0) {
        if (bid & 1) {
            do_gather(nb, out, sm_raw, gc, bid, t, w, lane);
            __syncthreads();
            do_transpose(x, sm_raw, tc, bid, w, lane);
        } else {
            do_transpose(x, sm_raw, tc, bid, w, lane);
            __syncthreads();
            do_gather(nb, out, sm_raw, gc, bid, t, w, lane);
        }
    } else if (tc >= 0) {
        do_transpose(x, sm_raw, tc, bid, w, lane);
    } else {
        do_gather(nb, out, sm_raw, gc, bid, t, w, lane);
    }
}

// ---------------------------------------------------------------------------
extern "C" void kernel_launch(void* const* d_in, const int* in_sizes, int n_in,
                              void* d_out, int out_size) {
    const float* x   = (const float*)d_in[0];
    const int*   nb  = (const int*)d_in[1];
    float*       out = (float*)d_out;

    (void)in_sizes; (void)n_in; (void)out_size;

    pool_kernel<<<GRID, 256>>>(x, nb, out, -1, 0);               // T0
    for (int c = 0; c < NCHUNK - 1; c++)
        pool_kernel<<<GRID, 256>>>(x, nb, out, c, c + 1);        // fused Gc+Tc+1
    pool_kernel<<<GRID, 256>>>(x, nb, out, NCHUNK - 1, -1);      // G_last
}